// round 5
// baseline (speedup 1.0000x reference)
#include <cuda_runtime.h>
#include <cstdint>

#define NN 200000
#define NE 600000
#define F  128
#define G3 384

// ---------------- scratch (device globals; no allocation allowed) ----------------
__device__ __align__(16) int   g_deg[NN];
__device__ __align__(16) float g_s[NN];
__device__ __align__(16) float g_tws0[F];        // rowsums of attend_w0
__device__ __align__(16) float g_whh0rs[G3];     // rowsums of whh0
__device__ __align__(16) float g_cs[(size_t)NN * F];      // cs0, later cs1
__device__ __align__(16) float g_x1[(size_t)NN * F];      // layer-0 output
__device__ __align__(16) float g_bufA[(size_t)NN * G3];   // gi0, later gi1
__device__ __align__(16) float g_bufB[(size_t)NN * G3];   // gh1
__device__ int g_e64;                                     // edge_index dtype flag

// device-side scratch selector (host never takes symbol addresses)
__device__ __forceinline__ float* buf_sel(int s) {
    switch (s) {
        case 0:  return g_cs;
        case 1:  return g_x1;
        case 2:  return g_bufA;
        default: return g_bufB;
    }
}

// ---------------- helpers ----------------
__device__ __forceinline__ float sigmf_(float x) { return 1.0f / (1.0f + expf(-x)); }
__device__ __forceinline__ float eluf_(float x)  { return x > 0.0f ? x : expm1f(x); }

__device__ __forceinline__ unsigned long long pack2(float f) {
    unsigned long long r;
    asm("mov.b64 %0, {%1, %1};" : "=l"(r) : "f"(f));
    return r;
}
__device__ __forceinline__ void fma2(unsigned long long& d, unsigned long long a, unsigned long long b) {
    asm("fma.rn.f32x2 %0, %1, %2, %0;" : "+l"(d) : "l"(a), "l"(b));
}
__device__ __forceinline__ float2 unpack2(unsigned long long v) {
    float2 r;
    asm("mov.b64 {%0, %1}, %2;" : "=f"(r.x), "=f"(r.y) : "l"(v));
    return r;
}

// ---------------- small kernels ----------------
// Detect edge_index element width. If stored as int64 (little-endian, values in
// [0, NN)), every odd int32 word is a zero hi-word. If int32, odd words are
// ordinary indices (first 256 all being zero is impossible for random data).
__global__ void k_detect(const int* __restrict__ ei32) {
    __shared__ int any;
    if (threadIdx.x == 0) any = 0;
    __syncthreads();
    if (ei32[2 * threadIdx.x + 1] != 0) atomicExch(&any, 1);
    __syncthreads();
    if (threadIdx.x == 0) g_e64 = (any == 0) ? 1 : 0;
}

__global__ void k_zero() {
    int i = blockIdx.x * blockDim.x + threadIdx.x;
    if (i < NN) g_deg[i] = 0;
}

// degree histogram over dst = edge_index[1]; layout-aware, bounds-guarded
__global__ void k_hist(const int* __restrict__ ei32) {
    int e = blockIdx.x * blockDim.x + threadIdx.x;
    if (e >= NE) return;
    long long v;
    if (g_e64) v = ((const long long*)ei32)[NE + e];
    else       v = (long long)ei32[NE + e];
    unsigned int u = (unsigned int)v;
    if (u < NN) atomicAdd(&g_deg[u], 1);
}

// warp per row: rows 0..127 -> rowsum(tw0); rows 128..511 -> rowsum(whh0)
__global__ void k_prep(const float* __restrict__ tw0, const float* __restrict__ whh0) {
    int w = (blockIdx.x * blockDim.x + threadIdx.x) >> 5;
    int lane = threadIdx.x & 31;
    if (w >= F + G3) return;
    const float* row = (w < F) ? (tw0 + (size_t)w * F) : (whh0 + (size_t)(w - F) * F);
    float4 v = ((const float4*)row)[lane];
    float s = v.x + v.y + v.z + v.w;
    #pragma unroll
    for (int o = 16; o; o >>= 1) s += __shfl_xor_sync(0xffffffffu, s, o);
    if (lane == 0) {
        if (w < F) g_tws0[w] = s;
        else       g_whh0rs[w - F] = s;
    }
}

// warp per node: s = rowsum(x[i]); cs0[i,:] = elu(s*tws0 + tb0)
__global__ void k_l0node(const float* __restrict__ x, const float* __restrict__ tb0) {
    int w = (blockIdx.x * blockDim.x + threadIdx.x) >> 5;
    int lane = threadIdx.x & 31;
    if (w >= NN) return;
    float4 v = ((const float4*)(x + (size_t)w * F))[lane];
    float s = v.x + v.y + v.z + v.w;
    #pragma unroll
    for (int o = 16; o; o >>= 1) s += __shfl_xor_sync(0xffffffffu, s, o);
    if (lane == 0) g_s[w] = s;
    float4 tw = ((const float4*)g_tws0)[lane];
    float4 tb = ((const float4*)tb0)[lane];
    float4 c;
    c.x = eluf_(fmaf(s, tw.x, tb.x));
    c.y = eluf_(fmaf(s, tw.y, tb.y));
    c.z = eluf_(fmaf(s, tw.z, tb.z));
    c.w = eluf_(fmaf(s, tw.w, tb.w));
    ((float4*)(g_cs + (size_t)w * F))[lane] = c;
}

// layer-0 GRU epilogue: gh is closed-form (s * rowsum(whh0) + bhh0), h = s
__global__ void k_gru0(const float* __restrict__ bhh0) {
    int idx = blockIdx.x * blockDim.x + threadIdx.x;
    if (idx >= NN * F) return;
    int i = idx >> 7, j = idx & 127;
    float s = g_s[i];
    float dg = (float)g_deg[i];
    const float* gi = g_bufA + (size_t)i * G3;
    float ir = gi[j], iz = gi[j + 128], inn = gi[j + 256];
    float hr = fmaf(s, g_whh0rs[j],       bhh0[j]);
    float hz = fmaf(s, g_whh0rs[j + 128], bhh0[j + 128]);
    float hn = fmaf(s, g_whh0rs[j + 256], bhh0[j + 256]);
    float r = sigmf_(ir + hr);
    float z = sigmf_(iz + hz);
    float n = tanhf(fmaf(r, hn, inn));
    g_x1[idx] = dg * ((1.0f - z) * n + z * s);
}

// layer-1 GRU epilogue: gi1 in bufA (bias incl), gh1 in bufB (bias incl), h = x1
__global__ void k_gru1(float* __restrict__ out) {
    int idx = blockIdx.x * blockDim.x + threadIdx.x;
    if (idx >= NN * F) return;
    int i = idx >> 7, j = idx & 127;
    float h = g_x1[idx];
    float dg = (float)g_deg[i];
    const float* gi = g_bufA + (size_t)i * G3;
    const float* gh = g_bufB + (size_t)i * G3;
    float r = sigmf_(gi[j] + gh[j]);
    float z = sigmf_(gi[j + 128] + gh[j + 128]);
    float n = tanhf(fmaf(r, gh[j + 256], gi[j + 256]));
    out[idx] = dg * ((1.0f - z) * n + z * h);
}

// ---------------- fp32 GEMM, K=128 fixed, f32x2 packed FMA ----------------
// C slab [n0, n0+128) = A[M,128] @ W^T + bias  (W row-major [N,128])
// BM=128, BN=128, BK=32 chunks; static shared only.
#define LDT 132
#define BK  32

__global__ __launch_bounds__(256, 1)
void k_gemm(int selA, const float* __restrict__ W,
            const float* __restrict__ bias, int selC,
            int M, int ldc, int act)
{
    __shared__ float As[BK * LDT];   // k-major: As[k][m]
    __shared__ float Ws[BK * LDT];   // k-major: Ws[k][n]

    const float* A = buf_sel(selA);
    float* C = buf_sel(selC);

    const int t = threadIdx.x;
    const int m0 = blockIdx.x * 128;
    const int n0 = blockIdx.y * 128;
    const float* Wp = W + (size_t)n0 * F;

    const int tx = t & 15, ty = t >> 4;
    const int ma = ty * 8, na = tx * 8;

    unsigned long long acc[4][8];
    #pragma unroll
    for (int p = 0; p < 4; p++)
        #pragma unroll
        for (int n = 0; n < 8; n++) acc[p][n] = 0ull;

    const int lm = t >> 3;            // base row (0..31), +32 per r
    const int lkb = (t & 7) << 2;     // k within chunk (0,4,...,28)

    for (int c = 0; c < 4; c++) {
        int kc = c * BK;
        #pragma unroll
        for (int r = 0; r < 4; r++) {
            int m = lm + r * 32;
            int gm = m0 + m;
            float4 v = make_float4(0.f, 0.f, 0.f, 0.f);
            if (gm < M) v = *(const float4*)(A + (size_t)gm * F + kc + lkb);
            As[(lkb + 0) * LDT + m] = v.x;
            As[(lkb + 1) * LDT + m] = v.y;
            As[(lkb + 2) * LDT + m] = v.z;
            As[(lkb + 3) * LDT + m] = v.w;
            float4 wv = *(const float4*)(Wp + (size_t)m * F + kc + lkb);
            Ws[(lkb + 0) * LDT + m] = wv.x;
            Ws[(lkb + 1) * LDT + m] = wv.y;
            Ws[(lkb + 2) * LDT + m] = wv.z;
            Ws[(lkb + 3) * LDT + m] = wv.w;
        }
        __syncthreads();

        #pragma unroll 4
        for (int k = 0; k < BK; k++) {
            const float* ak = As + k * LDT + ma;   // m-pairs load pre-packed
            unsigned long long aa[4];
            aa[0] = *(const unsigned long long*)(ak + 0);
            aa[1] = *(const unsigned long long*)(ak + 2);
            aa[2] = *(const unsigned long long*)(ak + 4);
            aa[3] = *(const unsigned long long*)(ak + 6);
            const float* bk = Ws + k * LDT + na;
            float4 b0 = *(const float4*)(bk);
            float4 b1 = *(const float4*)(bk + 4);
            unsigned long long bb[8];
            bb[0] = pack2(b0.x); bb[1] = pack2(b0.y); bb[2] = pack2(b0.z); bb[3] = pack2(b0.w);
            bb[4] = pack2(b1.x); bb[5] = pack2(b1.y); bb[6] = pack2(b1.z); bb[7] = pack2(b1.w);
            #pragma unroll
            for (int p = 0; p < 4; p++)
                #pragma unroll
                for (int n = 0; n < 8; n++) fma2(acc[p][n], aa[p], bb[n]);
        }
        __syncthreads();
    }

    float bv[8];
    #pragma unroll
    for (int n = 0; n < 8; n++) bv[n] = bias[n0 + na + n];

    #pragma unroll
    for (int p = 0; p < 4; p++) {
        int row0 = m0 + ma + 2 * p;
        float o0[8], o1[8];
        #pragma unroll
        for (int n = 0; n < 8; n++) {
            float2 v = unpack2(acc[p][n]);
            o0[n] = v.x + bv[n];
            o1[n] = v.y + bv[n];
        }
        if (act) {
            #pragma unroll
            for (int n = 0; n < 8; n++) { o0[n] = eluf_(o0[n]); o1[n] = eluf_(o1[n]); }
        }
        if (row0 < M) {
            float* c = C + (size_t)row0 * ldc + n0 + na;
            *(float4*)(c)     = make_float4(o0[0], o0[1], o0[2], o0[3]);
            *(float4*)(c + 4) = make_float4(o0[4], o0[5], o0[6], o0[7]);
        }
        if (row0 + 1 < M) {
            float* c = C + (size_t)(row0 + 1) * ldc + n0 + na;
            *(float4*)(c)     = make_float4(o1[0], o1[1], o1[2], o1[3]);
            *(float4*)(c + 4) = make_float4(o1[4], o1[5], o1[6], o1[7]);
        }
    }
}

// ---------------- host ----------------
extern "C" void kernel_launch(void* const* d_in, const int* in_sizes, int n_in,
                              void* d_out, int out_size)
{
    (void)in_sizes; (void)n_in; (void)out_size;
    const float* x    = (const float*)d_in[0];
    const int*   ei   = (const int*)d_in[1];   // int32 or int64 storage; probed on device
    // d_in[2], d_in[3] = align_w0/b0 -> dead (softmax over size-1 axis == 1)
    const float* tw0  = (const float*)d_in[4];
    const float* tb0  = (const float*)d_in[5];
    const float* wih0 = (const float*)d_in[6];
    const float* whh0 = (const float*)d_in[7];
    const float* bih0 = (const float*)d_in[8];
    const float* bhh0 = (const float*)d_in[9];
    const float* tw1  = (const float*)d_in[12];
    const float* tb1  = (const float*)d_in[13];
    const float* wih1 = (const float*)d_in[14];
    const float* whh1 = (const float*)d_in[15];
    const float* bih1 = (const float*)d_in[16];
    const float* bhh1 = (const float*)d_in[17];
    float* out = (float*)d_out;

    // edge dtype probe + degree histogram (edge_index row 1 = dst)
    k_detect<<<1, 256>>>(ei);
    k_zero<<<(NN + 255) / 256, 256>>>();
    k_hist<<<(NE + 255) / 256, 256>>>(ei);
    // weight rowsums for the rank-1 layer-0 structure
    k_prep<<<64, 256>>>(tw0, whh0);
    // layer 0: s + cs0 (-> g_cs)
    k_l0node<<<NN / 8, 256>>>(x, tb0);

    dim3 g3((NN + 127) / 128, 3), g1((NN + 127) / 128, 1);
    // gi0 = cs0 @ wih0^T + bih0          (A=g_cs, C=g_bufA)
    k_gemm<<<g3, 256>>>(0, wih0, bih0, 2, NN, G3, 0);
    // layer-0 GRU -> x1 = deg * m        (-> g_x1)
    k_gru0<<<(NN * F + 255) / 256, 256>>>(bhh0);
    // cs1 = elu(x1 @ tw1^T + tb1)        (A=g_x1, C=g_cs)
    k_gemm<<<g1, 256>>>(1, tw1, tb1, 0, NN, F, 1);
    // gh1 = x1 @ whh1^T + bhh1           (A=g_x1, C=g_bufB)
    k_gemm<<<g3, 256>>>(1, whh1, bhh1, 3, NN, G3, 0);
    // gi1 = cs1 @ wih1^T + bih1          (A=g_cs, C=g_bufA)
    k_gemm<<<g3, 256>>>(0, wih1, bih1, 2, NN, G3, 0);
    // layer-1 GRU -> out = deg * m
    k_gru1<<<(NN * F + 255) / 256, 256>>>(out);
}